// round 12
// baseline (speedup 1.0000x reference)
#include <cuda_runtime.h>
#include <cuda_fp16.h>

// ---------------- problem constants ----------------
#define NBATCH 65536
#define NNODE  10
#define KD     512
#define HD     64
#define NC     128
#define MROWS  (NBATCH * NNODE)            // 655360
#define BPC    12                          // batches per CTA
#define RPC    120                         // valid rows per CTA
#define NCTA   ((NBATCH + BPC - 1) / BPC)  // 5462 (last tile: 4 batches)
#define NCHUNK 16                          // K chunks of 32

// W1 -> fp16, layout [k_phys][n] with k16-slot permutation baked in (see convB).
__device__ __align__(128) __half g_Bh[KD * NC];
// Zero-padded copy of X's last 40 rows (tail tile reads this; rows 40..127 = 0).
__device__ __align__(256) float g_Xtail[128 * KD];

__constant__ int c_I[45] = {0,0,0,0,0,0,0,0,0, 1,1,1,1,1,1,1,1, 2,2,2,2,2,2,2,
                            3,3,3,3,3,3, 4,4,4,4,4, 5,5,5,5, 6,6,6, 7,7, 8};
__constant__ int c_J[45] = {1,2,3,4,5,6,7,8,9, 2,3,4,5,6,7,8,9, 3,4,5,6,7,8,9,
                            4,5,6,7,8,9, 5,6,7,8,9, 6,7,8,9, 7,8,9, 8,9, 9};

// ---------------- smem layout (dynamic) ----------------
#define OFF_SB1   0
#define OFF_SW2   256
#define OFF_SB2   512
#define OFF_BSTG  1024
#define BROW      272
#define STAGE_SZ  (32 * BROW)              // 8704
#define OFF_SP    (OFF_BSTG + 2 * STAGE_SZ)       // 18432
#define SP_STRIDE 132
#define OFF_VBUF  (OFF_SP + 128 * SP_STRIDE * 4)  // 86016
#define SMEM_BYTES (OFF_VBUF + 540 * 4 + 16)      // 88192

__device__ __forceinline__ unsigned smem_u32(const void* p) {
    unsigned a;
    asm("{ .reg .u64 t; cvta.to.shared.u64 t, %1; cvt.u32.u64 %0, t; }" : "=r"(a) : "l"(p));
    return a;
}
__device__ __forceinline__ void cp16(unsigned dst, const void* src) {
    asm volatile("cp.async.cg.shared.global [%0], [%1], 16;" :: "r"(dst), "l"(src) : "memory");
}
#define CP_COMMIT() asm volatile("cp.async.commit_group;" ::: "memory")
#define CP_WAIT0()  asm volatile("cp.async.wait_group 0;" ::: "memory")

#define LDMX4T(r0, r1, r2, r3, addr) \
    asm volatile("ldmatrix.sync.aligned.m8n8.x4.trans.shared.b16 {%0,%1,%2,%3}, [%4];" \
                 : "=r"(r0), "=r"(r1), "=r"(r2), "=r"(r3) : "r"(addr))

#define MMA16816(d, a0, a1, a2, a3, b0, b1) \
    asm volatile("mma.sync.aligned.m16n8k16.row.col.f32.f16.f16.f32 " \
                 "{%0,%1,%2,%3},{%4,%5,%6,%7},{%8,%9},{%0,%1,%2,%3};" \
                 : "+f"((d)[0]), "+f"((d)[1]), "+f"((d)[2]), "+f"((d)[3]) \
                 : "r"(a0), "r"(a1), "r"(a2), "r"(a3), "r"(b0), "r"(b1))

// streaming LDG.128 (evict-first): X has zero reuse
__device__ __forceinline__ float4 ldg128_cs(const void* p) {
    float4 v;
    asm volatile("ld.global.cs.v4.f32 {%0,%1,%2,%3}, [%4];"
                 : "=f"(v.x), "=f"(v.y), "=f"(v.z), "=f"(v.w) : "l"(p));
    return v;
}
__device__ __forceinline__ unsigned pack2(float x, float y) {
    __half2 t = __floats2half2_rn(x, y);
    return *(unsigned*)&t;
}

// ---------------- kernel 0: W1 -> fp16, [k][n], with k16 permutation ----------------
// Fragment k-slots: logical ks (4t..4t+3) of a k16 half occupy mma slots
// (2t, 2t+1, 2t+8, 2t+9). Same permutation as before (A fragment k-map unchanged).
__global__ void convB_kernel(const float* __restrict__ W1) {
    int idx = blockIdx.x * 256 + threadIdx.x;      // logical k*128 + n
    if (idx >= KD * NC) return;
    int k = idx >> 7, n = idx & 127;
    float w = W1[((long long)k + (n >= HD ? KD : 0)) * HD + (n & (HD - 1))];
    int kk = k & 15, t = kk >> 2, d = kk & 3;
    int phys = (k & ~15) + t * 2 + (d & 1) + ((d >= 2) ? 8 : 0);
    g_Bh[phys * NC + n] = __float2half_rn(w);
}

// ---------------- kernel 0b: copy X tail rows (40 valid) into padded buffer ----------------
__global__ void tailX_kernel(const float* __restrict__ X) {
    int i = blockIdx.x * 256 + threadIdx.x;        // 0 .. 128*512-1
    if (i >= 128 * KD) return;
    int r = i >> 9;
    g_Xtail[i] = (r < 40) ? X[(long long)((NCTA - 1) * RPC + r) * KD + (i & 511)] : 0.0f;
}

// ---------------- fused GEMM (full-line A loads + butterfly exchange) ----------------
__global__ __launch_bounds__(256, 2)
void gemm_pair_kernel(const float* __restrict__ X,
                      const float* __restrict__ b1, const float* __restrict__ W2,
                      const float* __restrict__ b2, float* __restrict__ out) {
    extern __shared__ char smem[];
    const unsigned sb = smem_u32(smem);
    const int tid  = threadIdx.x;
    const int warp = tid >> 5;
    const int lane = tid & 31;
    const int wm   = warp & 3;      // 4 M-groups of 32 rows
    const int wn   = warp >> 2;     // 2 N-groups of 64 cols
    const int gid  = lane >> 2;     // 0..7
    const int tig  = lane & 3;      // 0..3
    const unsigned b4 = (lane >> 4) & 1;   // row-half / k-chunk selector
    const long long tile = blockIdx.x;

    if (tid < HD) {
        ((float*)(smem + OFF_SB1))[tid] = b1[tid];
        ((float*)(smem + OFF_SW2))[tid] = W2[tid];
    }
    if (tid == 0) ((float*)(smem + OFF_SB2))[0] = b2[0];

    // ---- A base pointer: full-line loads ----
    // LDG q (q=0..7): lane loads row  wm*32 + (gid&3) + 4q,  k16B-chunk c16 = tig + 4*b4.
    // One LDG warp-instruction = 4 rows x 128B = 4 full lines (4 wavefronts).
    // Tail tile reads the zero-padded g_Xtail copy -> no clamping anywhere.
    const char* apc;
    {
        const char* xb = (tile == NCTA - 1) ? (const char*)g_Xtail
                                            : (const char*)X + (size_t)tile * RPC * KD * 4;
        apc = xb + (unsigned)((wm * 32 + (gid & 3)) * (KD * 4) + (tig + 4 * b4) * 16);
    }

    // ---- B cp.async coordinates ----
    const int bk = tid >> 3;
    const int bg = tid & 7;
    const unsigned bdst0 = (unsigned)(bk * BROW + bg * 16);
    const __half* bsrc = g_Bh + bk * NC + bg * 8;

    // ---- ldmatrix lane address (within stage) ----
    const unsigned sel   = lane >> 3;
    const unsigned rowin = lane & 7;
    const unsigned ldm_l = ((sel & 1) * 8 + rowin) * BROW + (wn * 64 + (sel >> 1) * 8) * 2;

    float acc[2][8][4];
    #pragma unroll
    for (int i = 0; i < 2; i++)
        #pragma unroll
        for (int j = 0; j < 8; j++)
            #pragma unroll
            for (int q = 0; q < 4; q++) acc[i][j][q] = 0.0f;

    float4 fb[8];        // raw chunk (8 full-line LDG.128)
    unsigned FR[16];     // fragments: [half h][i][slot] = FR[h*8 + i*4 + slot]

    // convert + butterfly-exchange fb -> FR
    auto cvtshfl = [&]() {
        #pragma unroll
        for (int s = 0; s < 4; s++) {
            float4 e = fb[2 * s], o = fb[2 * s + 1];
            unsigned e0 = pack2(e.x, e.y), e1 = pack2(e.z, e.w);
            unsigned o0 = pack2(o.x, o.y), o1 = pack2(o.z, o.w);
            // lane sends its partner's-rows data; receives its own-rows other k-chunk
            unsigned s0 = b4 ? e0 : o0, s1 = b4 ? e1 : o1;
            unsigned r0 = __shfl_xor_sync(0xffffffffu, s0, 16);
            unsigned r1 = __shfl_xor_sync(0xffffffffu, s1, 16);
            const int i = s >> 1, r = s & 1;
            FR[i * 4 + r]         = b4 ? r0 : e0;   // half0 (k-chunk lo)
            FR[i * 4 + r + 2]     = b4 ? r1 : e1;
            FR[8 + i * 4 + r]     = b4 ? o0 : r0;   // half1 (k-chunk hi)
            FR[8 + i * 4 + r + 2] = b4 ? o1 : r1;
        }
    };

    // ---- prologue: B chunk0 staged; A chunk0 loaded + converted ----
    cp16(sb + OFF_BSTG + bdst0,       bsrc);
    cp16(sb + OFF_BSTG + bdst0 + 128, bsrc + 64);
    CP_COMMIT();
    #pragma unroll
    for (int q = 0; q < 8; q++) fb[q] = ldg128_cs(apc + q * 8192);
    cvtshfl();
    CP_WAIT0();
    __syncthreads();

    // ---- main loop over 16 chunks of k=32 ----
    #pragma unroll 1
    for (int c = 0; c < NCHUNK; ++c) {
        const unsigned stg = sb + OFF_BSTG + (c & 1) * STAGE_SZ;

        if (c + 1 < NCHUNK) {
            const unsigned nstg = sb + OFF_BSTG + ((c + 1) & 1) * STAGE_SZ;
            const __half* src = bsrc + (c + 1) * 32 * NC;
            cp16(nstg + bdst0,       src);
            cp16(nstg + bdst0 + 128, src + 64);
            CP_COMMIT();
            apc += 128;
            #pragma unroll
            for (int q = 0; q < 8; q++) fb[q] = ldg128_cs(apc + q * 8192);
        }

        // ---- mma chunk c ----
        #pragma unroll
        for (int h = 0; h < 2; h++) {
            const unsigned ab = stg + ldm_l + (unsigned)h * (16 * BROW);
            const unsigned* Ar = FR + h * 8;
            #pragma unroll
            for (int jj = 0; jj < 4; jj++) {
                unsigned q0, q1, q2, q3;
                LDMX4T(q0, q1, q2, q3, ab + jj * 32);
                #pragma unroll
                for (int i = 0; i < 2; i++) {
                    MMA16816(acc[i][2 * jj],     Ar[i * 4 + 0], Ar[i * 4 + 1], Ar[i * 4 + 2], Ar[i * 4 + 3], q0, q1);
                    MMA16816(acc[i][2 * jj + 1], Ar[i * 4 + 0], Ar[i * 4 + 1], Ar[i * 4 + 2], Ar[i * 4 + 3], q2, q3);
                }
            }
        }

        if (c + 1 < NCHUNK) cvtshfl();   // build fragments for chunk c+1
        CP_WAIT0();
        __syncthreads();
    }

    // ---- epilogue: acc -> sp[128][132] ----
    float* sp = (float*)(smem + OFF_SP);
    #pragma unroll
    for (int i = 0; i < 2; i++)
        #pragma unroll
        for (int j = 0; j < 8; j++) {
            int r = wm * 32 + i * 16 + gid;
            int c = wn * 64 + j * 8 + 2 * tig;
            *(float2*)(sp + r * SP_STRIDE + c)       = make_float2(acc[i][j][0], acc[i][j][1]);
            *(float2*)(sp + (r + 8) * SP_STRIDE + c) = make_float2(acc[i][j][2], acc[i][j][3]);
        }
    __syncthreads();

    // ---- pair compute (float4-vectorized) ----
    const int nb = (int)min((long long)BPC, (long long)NBATCH - tile * BPC);
    float* vbuf = (float*)(smem + OFF_VBUF);
    const float4* b14 = (const float4*)(smem + OFF_SB1);
    const float4* w24 = (const float4*)(smem + OFF_SW2);
    const float bias2 = ((const float*)(smem + OFF_SB2))[0];

    for (int p = tid; p < nb * 45; p += 256) {
        int bb = p / 45, q = p - bb * 45;
        const float4* pi4 = (const float4*)(sp + (bb * NNODE + c_I[q]) * SP_STRIDE);       // pa
        const float4* pj4 = (const float4*)(sp + (bb * NNODE + c_J[q]) * SP_STRIDE + HD);  // pb
        float a2 = 0.0f;
        #pragma unroll
        for (int h4 = 0; h4 < HD / 4; h4++) {
            float4 a = pi4[h4], b = pj4[h4], c = b14[h4], w = w24[h4];
            a2 = fmaf(fmaxf(a.x + b.x + c.x, 0.0f), w.x, a2);
            a2 = fmaf(fmaxf(a.y + b.y + c.y, 0.0f), w.y, a2);
            a2 = fmaf(fmaxf(a.z + b.z + c.z, 0.0f), w.z, a2);
            a2 = fmaf(fmaxf(a.w + b.w + c.w, 0.0f), w.w, a2);
        }
        vbuf[p] = a2 + bias2;
    }
    __syncthreads();

    // ---- symmetric scatter ----
    for (int o = tid; o < nb * 100; o += 256) {
        int bb = o / 100, cell = o - bb * 100;
        int n1 = cell / 10, n2 = cell % 10;
        float val = 0.0f;
        if (n1 != n2) {
            int i = n1 < n2 ? n1 : n2;
            int j = n1 < n2 ? n2 : n1;
            val = vbuf[bb * 45 + 9 * i - (i * (i - 1)) / 2 + (j - i - 1)];
        }
        out[(tile * BPC + bb) * 100 + cell] = val;
    }
}

extern "C" void kernel_launch(void* const* d_in, const int* in_sizes, int n_in,
                              void* d_out, int out_size) {
    const float* X  = (const float*)d_in[0];
    const float* W1 = (const float*)d_in[1];
    const float* b1 = (const float*)d_in[2];
    const float* W2 = (const float*)d_in[3];
    const float* b2 = (const float*)d_in[4];
    float* out = (float*)d_out;

    cudaFuncSetAttribute(gemm_pair_kernel,
                         cudaFuncAttributeMaxDynamicSharedMemorySize, SMEM_BYTES);

    convB_kernel<<<(KD * NC + 255) / 256, 256>>>(W1);
    tailX_kernel<<<(128 * KD + 255) / 256, 256>>>(X);
    gemm_pair_kernel<<<NCTA, 256, SMEM_BYTES>>>(X, b1, W2, b2, out);
}